// round 14
// baseline (speedup 1.0000x reference)
#include <cuda_runtime.h>
#include <cuda_fp16.h>
#include <cstdint>

#define NROWS  131072
#define DIMD   512
#define KCOLS  1024
#define MT     64         // rows per CTA (2 CTAs/SM)
#define NT     128        // cols per tile
#define KB     64         // d per chunk
#define NTILES (KCOLS/NT) // 8
#define DCH    (DIMD/KB)  // 8
#define NIT    (NTILES*DCH)  // 64
#define THREADS 256
#define NSTAGE 3          // B-only stages

// smem layout
#define SM_CSQ   0                    // 128 floats
#define SM_A     1024                 // resident A: 8 chunk sub-arrays of 8KB
#define A_SUB    8192                 // [64 rows][64 d] half, sw128
#define A_BYTES  (DCH*A_SUB)          // 65536
#define SM_B     (SM_A + A_BYTES)     // 66560
#define B_SUB    16384                // [128 cols][64 d] half, sw128
#define SMEM_TOTAL (SM_B + NSTAGE*B_SUB)   // 115712 -> 2 CTAs/SM = 231424

// ------------- device globals (no allocations allowed) -------------
__device__ __align__(128) __half g_Ahi[(size_t)NROWS*DIMD];
__device__ __align__(128) __half g_Bhi[(size_t)KCOLS*DIMD];   // fp16 transposed [k][d]
__device__ __align__(128) float  g_Bt[(size_t)KCOLS*DIMD];    // fp32 transposed [k][d]
__device__ float g_csq[KCOLS];
__device__ int4  g_cand[NROWS];

// ------------- helpers -------------
__device__ __forceinline__ uint32_t smem_u32(const void* p) {
    uint32_t a;
    asm("{ .reg .u64 t; cvta.to.shared.u64 t, %1; cvt.u32.u64 %0, t; }" : "=r"(a) : "l"(p));
    return a;
}
__device__ __forceinline__ uint32_t sw128(uint32_t o) { return o ^ ((o >> 3) & 0x70); }

__device__ __forceinline__ void cp16(uint32_t s, const void* g) {
    size_t ga = __cvta_generic_to_global(g);
    asm volatile("cp.async.cg.shared.global [%0], [%1], 16;" :: "r"(s), "l"(ga) : "memory");
}

#define LDM_X4(r0,r1,r2,r3,addr) \
    asm volatile("ldmatrix.sync.aligned.m8n8.x4.shared.b16 {%0,%1,%2,%3}, [%4];" \
        : "=r"(r0),"=r"(r1),"=r"(r2),"=r"(r3) : "r"(addr))

#define MMA16816(d, a, b0, b1) \
    asm volatile("mma.sync.aligned.m16n8k16.row.col.f32.f16.f16.f32 " \
        "{%0,%1,%2,%3},{%4,%5,%6,%7},{%8,%9},{%0,%1,%2,%3};" \
        : "+f"((d)[0]),"+f"((d)[1]),"+f"((d)[2]),"+f"((d)[3]) \
        : "r"((a)[0]),"r"((a)[1]),"r"((a)[2]),"r"((a)[3]),"r"(b0),"r"(b1))

// ------------- precompute kernels -------------
__global__ void split_feat(const float* __restrict__ A) {
    size_t i = (size_t)blockIdx.x * blockDim.x + threadIdx.x;   // 8 elems each
    if (i >= (size_t)NROWS * DIMD / 8) return;
    const float4* a4 = reinterpret_cast<const float4*>(A) + i * 2;
    float4 v0 = a4[0], v1 = a4[1];
    float x[8] = {v0.x, v0.y, v0.z, v0.w, v1.x, v1.y, v1.z, v1.w};
    __half h[8];
    #pragma unroll
    for (int j = 0; j < 8; j++) h[j] = __float2half_rn(x[j]);
    reinterpret_cast<uint4*>(g_Ahi)[i] = *reinterpret_cast<uint4*>(h);
}

// 32x32 smem tile transpose: B [d][k] -> g_Bt/g_Bhi [k][d], coalesced both sides
__global__ __launch_bounds__(256) void split_cent(const float* __restrict__ B) {
    __shared__ float tile[32][33];
    const int k0 = (blockIdx.x & 31) * 32;
    const int d0 = (blockIdx.x >> 5) * 32;
    const int tx = threadIdx.x & 31;
    const int ty = threadIdx.x >> 5;          // 0..7
    #pragma unroll
    for (int j = 0; j < 32; j += 8)
        tile[ty + j][tx] = B[(size_t)(d0 + ty + j) * KCOLS + k0 + tx];
    __syncthreads();
    #pragma unroll
    for (int j = 0; j < 32; j += 8) {
        float v = tile[tx][ty + j];
        size_t o = (size_t)(k0 + ty + j) * DIMD + d0 + tx;
        g_Bt[o]  = v;
        g_Bhi[o] = __float2half_rn(v);
    }
}

// one warp per centroid, reads contiguous g_Bt rows
__global__ __launch_bounds__(256) void csq_kernel() {
    const int k = blockIdx.x * 8 + (threadIdx.x >> 5);
    const int lane = threadIdx.x & 31;
    const float4* b4 = reinterpret_cast<const float4*>(g_Bt + (size_t)k * DIMD);
    float s = 0.f;
    #pragma unroll
    for (int i = 0; i < 4; i++) {
        float4 v = b4[lane + 32 * i];
        s = fmaf(v.x, v.x, s); s = fmaf(v.y, v.y, s);
        s = fmaf(v.z, v.z, s); s = fmaf(v.w, v.w, s);
    }
    #pragma unroll
    for (int o = 16; o > 0; o >>= 1) s += __shfl_xor_sync(0xFFFFFFFFu, s, o);
    if (lane == 0) g_csq[k] = s;
}

// ------------- phase 1: A-resident fp16 screen + top-2/thread -> top-4/row -------------
__global__ __launch_bounds__(THREADS, 2) void assign_mma() {
    extern __shared__ char smem[];
    const uint32_t sb = smem_u32(smem);
    const int tid = threadIdx.x;
    const int lane = tid & 31;
    const int w = tid >> 5;
    const int mw = w >> 2;          // 0..1 (M)
    const int nw = w & 3;           // 0..3 (N)
    const int row0 = blockIdx.x * MT;
    float* csq_s = reinterpret_cast<float*>(smem + SM_CSQ);

    // ldmatrix address precomputes (within a 64-d sub-array)
    uint32_t aBase[2], aM[2], bBase[2], bM[2];
    #pragma unroll
    for (int mi = 0; mi < 2; mi++) {
        int r = mw * 32 + mi * 16 + (lane & 15);
        aBase[mi] = (uint32_t)r * 128;
        aM[mi] = (uint32_t)(r & 7) * 16;
    }
    #pragma unroll
    for (int nb = 0; nb < 2; nb++) {
        int r = nw * 32 + nb * 16 + ((lane & 7) + ((lane >> 4) << 3));
        bBase[nb] = (uint32_t)r * 128;
        bM[nb] = (uint32_t)(r & 7) * 16;
    }
    const uint32_t aU = (uint32_t)(lane >> 4) * 16;        // 0 or 16
    const uint32_t bU = (uint32_t)((lane >> 3) & 1) * 16;  // 0 or 16

    // per-thread cp.async source pointers (hoisted 64-bit address math)
    const __half* aSrc[2];
    const __half* bSrc[4];
    uint32_t soA[2], soB[4];
    #pragma unroll
    for (int q = 0; q < 2; q++) {
        int idx = tid + THREADS * q;
        int r = idx >> 3, u = idx & 7;
        soA[q] = sw128((uint32_t)r * 128 + (uint32_t)u * 16);
        aSrc[q] = g_Ahi + (size_t)(row0 + r) * DIMD + u * 8;
    }
    #pragma unroll
    for (int q = 0; q < 4; q++) {
        int idx = tid + THREADS * q;
        int r = idx >> 3, u = idx & 7;
        soB[q] = sw128((uint32_t)r * 128 + (uint32_t)u * 16);
        bSrc[q] = g_Bhi + (size_t)r * DIMD + u * 8;
    }

    float acc1[2][4][4];
    float v1[4], v2[4];
    int   i1[4], i2[4];
    #pragma unroll
    for (int i = 0; i < 4; i++) { v1[i] = 3.4e38f; v2[i] = 3.4e38f; i1[i] = 0; i2[i] = 0; }

    auto load_stage = [&](int stg, int it) {
        const int nt = it >> 3, dc = it & 7;
        const int bOff = nt * NT * DIMD + dc * KB;
        uint32_t sbase = sb + SM_B + (uint32_t)stg * B_SUB;
        #pragma unroll
        for (int q = 0; q < 4; q++) cp16(sbase + soB[q], bSrc[q] + bOff);
        asm volatile("cp.async.commit_group;" ::: "memory");
    };

    // ---- prologue: resident A (one commit group), then first B stages ----
    #pragma unroll
    for (int dc = 0; dc < DCH; dc++) {
        uint32_t abase = sb + SM_A + (uint32_t)dc * A_SUB;
        #pragma unroll
        for (int q = 0; q < 2; q++) cp16(abase + soA[q], aSrc[q] + dc * KB);
    }
    asm volatile("cp.async.commit_group;" ::: "memory");
    load_stage(0, 0);
    load_stage(1, 1);

    for (int it = 0; it < NIT; it++) {
        const int nt = it >> 3, dc = it & 7, stg = it % NSTAGE;
        asm volatile("cp.async.wait_group %0;" :: "n"(NSTAGE - 2) : "memory");
        __syncthreads();   // stage `it` (and A on it=0) arrived; slot being reloaded is free
        if (it + NSTAGE - 1 < NIT)
            load_stage((it + NSTAGE - 1) % NSTAGE, it + NSTAGE - 1);

        if (dc == 0) {
            if (tid < NT) csq_s[tid] = g_csq[nt * NT + tid];
            #pragma unroll
            for (int mi = 0; mi < 2; mi++)
                #pragma unroll
                for (int ni = 0; ni < 4; ni++)
                    #pragma unroll
                    for (int e = 0; e < 4; e++) acc1[mi][ni][e] = 0.f;
        }

        // ---- compute chunk: A from resident sub-array dc, B from stage ----
        const uint32_t subA = sb + SM_A + (uint32_t)dc * A_SUB;
        const uint32_t subB = sb + SM_B + (uint32_t)stg * B_SUB;
        #pragma unroll
        for (int k16 = 0; k16 < 4; k16++) {
            const uint32_t ka = (uint32_t)k16 * 32 + aU;
            const uint32_t kb = (uint32_t)k16 * 32 + bU;
            uint32_t ahi[2][4], bhi[2][4];
            #pragma unroll
            for (int mi = 0; mi < 2; mi++)
                LDM_X4(ahi[mi][0], ahi[mi][1], ahi[mi][2], ahi[mi][3],
                       subA + aBase[mi] + (ka ^ aM[mi]));
            #pragma unroll
            for (int nb = 0; nb < 2; nb++)
                LDM_X4(bhi[nb][0], bhi[nb][1], bhi[nb][2], bhi[nb][3],
                       subB + bBase[nb] + (kb ^ bM[nb]));
            #pragma unroll
            for (int mi = 0; mi < 2; mi++)
                #pragma unroll
                for (int ni = 0; ni < 4; ni++)
                    MMA16816(acc1[mi][ni], ahi[mi],
                             bhi[ni >> 1][(ni & 1) * 2], bhi[ni >> 1][(ni & 1) * 2 + 1]);
        }

        if (dc == DCH - 1) {
            // fold this column tile into per-thread top-2 (registers only)
            #pragma unroll
            for (int mi = 0; mi < 2; mi++)
                #pragma unroll
                for (int half = 0; half < 2; half++) {
                    const int rs = mi * 2 + half;
                    #pragma unroll
                    for (int ni = 0; ni < 4; ni++)
                        #pragma unroll
                        for (int e = 0; e < 2; e++) {
                            const int cl = nw * 32 + ni * 8 + (lane & 3) * 2 + e;
                            const int col = nt * NT + cl;
                            float dist = csq_s[cl] - 2.0f * acc1[mi][ni][half * 2 + e];
                            if (dist < v1[rs]) {
                                v2[rs] = v1[rs]; i2[rs] = i1[rs];
                                v1[rs] = dist;   i1[rs] = col;
                            } else if (dist < v2[rs]) {
                                v2[rs] = dist; i2[rs] = col;
                            }
                        }
                }
        }
    }
    __syncthreads();

    // ---- dump all per-thread top-2 to smem (reuse B stage area) ----
    float4* cand = reinterpret_cast<float4*>(smem + SM_B);
    {
        const int slot = nw * 4 + (lane & 3);
        #pragma unroll
        for (int rs = 0; rs < 4; rs++) {
            int row = mw * 32 + rs * 8 + (lane >> 2);
            cand[row * 16 + slot] = make_float4(v1[rs], __int_as_float(i1[rs]),
                                                v2[rs], __int_as_float(i2[rs]));
        }
    }
    __syncthreads();

    // ---- one thread per row: top-4 of 32 candidates (lexicographic) ----
    if (tid < MT) {
        float t1 = 3.4e38f, t2 = 3.4e38f, t3 = 3.4e38f, t4 = 3.4e38f;
        int   j1 = 0, j2 = 0, j3 = 0, j4 = 0;
        #pragma unroll 4
        for (int t = 0; t < 16; t++) {
            float4 c = cand[tid * 16 + t];
            #pragma unroll
            for (int h = 0; h < 2; h++) {
                float v = h ? c.z : c.x;
                int   i = __float_as_int(h ? c.w : c.y);
                if (v < t1 || (v == t1 && i < j1)) {
                    t4 = t3; j4 = j3; t3 = t2; j3 = j2; t2 = t1; j2 = j1; t1 = v; j1 = i;
                } else if (v < t2 || (v == t2 && i < j2)) {
                    t4 = t3; j4 = j3; t3 = t2; j3 = j2; t2 = v; j2 = i;
                } else if (v < t3 || (v == t3 && i < j3)) {
                    t4 = t3; j4 = j3; t3 = v; j3 = i;
                } else if (v < t4 || (v == t4 && i < j4)) {
                    t4 = v; j4 = i;
                }
            }
        }
        g_cand[row0 + tid] = make_int4(j1, j2, j3, j4);
    }
}

// ------------- phase 2: exact fp32 rescue — one warp per row, coalesced -------------
__global__ __launch_bounds__(256) void rescue_kernel(const float* __restrict__ A,
                                                     float* __restrict__ out) {
    const int row = blockIdx.x * 8 + (threadIdx.x >> 5);
    const int lane = threadIdx.x & 31;
    const int4 cd = g_cand[row];   // same addr across warp -> broadcast

    const float4* a4 = reinterpret_cast<const float4*>(A + (size_t)row * DIMD);
    float4 av[4];
    #pragma unroll
    for (int i = 0; i < 4; i++) av[i] = a4[lane + 32 * i];

    int cands[4] = {cd.x, cd.y, cd.z, cd.w};
    float bv = 3.4e38f;
    int   bi = 0x7FFFFFFF;
    #pragma unroll
    for (int c = 0; c < 4; c++) {
        const float4* b4 = reinterpret_cast<const float4*>(g_Bt + (size_t)cands[c] * DIMD);
        float s = 0.f;
        #pragma unroll
        for (int i = 0; i < 4; i++) {
            float4 bvq = b4[lane + 32 * i];   // coalesced; g_Bt is L2-hot (2MB)
            s = fmaf(av[i].x, bvq.x, s);
            s = fmaf(av[i].y, bvq.y, s);
            s = fmaf(av[i].z, bvq.z, s);
            s = fmaf(av[i].w, bvq.w, s);
        }
        #pragma unroll
        for (int o = 16; o > 0; o >>= 1) s += __shfl_xor_sync(0xFFFFFFFFu, s, o);
        float dist = g_csq[cands[c]] - 2.0f * s;
        if (dist < bv || (dist == bv && cands[c] < bi)) { bv = dist; bi = cands[c]; }
    }
    if (lane == 0) out[row] = (float)bi;
}

// ------------- launch -------------
extern "C" void kernel_launch(void* const* d_in, const int* in_sizes, int n_in,
                              void* d_out, int out_size) {
    const float* features  = (const float*)d_in[0];   // [131072, 512]
    const float* centroids = (const float*)d_in[1];   // [512, 1024]
    float* out = (float*)d_out;

    cudaFuncSetAttribute(assign_mma, cudaFuncAttributeMaxDynamicSharedMemorySize, SMEM_TOTAL);

    split_feat<<<(int)(((size_t)NROWS * DIMD / 8 + 255) / 256), 256>>>(features);
    split_cent<<<(KCOLS / 32) * (DIMD / 32), 256>>>(centroids);
    csq_kernel<<<KCOLS / 8, 256>>>();
    assign_mma<<<NROWS / MT, THREADS, SMEM_TOTAL>>>();
    rescue_kernel<<<NROWS / 8, 256>>>(features, out);
}

// round 15
// speedup vs baseline: 1.5314x; 1.5314x over previous
#include <cuda_runtime.h>
#include <cuda_fp16.h>
#include <cstdint>

#define NROWS  131072
#define DIMD   512
#define KCOLS  1024
#define MT     128        // rows per CTA
#define NT     128        // cols per tile
#define KB     64         // d per chunk
#define NTILES (KCOLS/NT) // 8
#define DCH    (DIMD/KB)  // 8
#define NIT    (NTILES*DCH)  // 64
#define THREADS 256       // 8 warps: 4 (M) x 2 (N), warp tile 32x64
#define NSTAGE 3

// smem layout
#define SM_CSQ   0                   // 128 floats
#define SM_TILES 1024
#define A_SUB    16384               // [128 rows][64 d] half, sw128
#define B_SUB    16384               // [128 cols][64 d] half, sw128
#define STAGE_B  (A_SUB + B_SUB)     // 32KB
#define SMEM_TOTAL (SM_TILES + NSTAGE*STAGE_B)   // 99328 -> 2 CTAs/SM

// ------------- device globals (no allocations allowed) -------------
__device__ __align__(128) __half g_Ahi[(size_t)NROWS*DIMD];
__device__ __align__(128) __half g_Bhi[(size_t)KCOLS*DIMD];   // fp16 transposed [k][d]
__device__ __align__(128) float  g_Bt[(size_t)KCOLS*DIMD];    // fp32 transposed [k][d]
__device__ float g_csq[KCOLS];
__device__ int4  g_cand[NROWS];

// ------------- helpers -------------
__device__ __forceinline__ uint32_t smem_u32(const void* p) {
    uint32_t a;
    asm("{ .reg .u64 t; cvta.to.shared.u64 t, %1; cvt.u32.u64 %0, t; }" : "=r"(a) : "l"(p));
    return a;
}
__device__ __forceinline__ uint32_t sw128(uint32_t o) { return o ^ ((o >> 3) & 0x70); }

__device__ __forceinline__ void cp16(uint32_t s, const void* g) {
    size_t ga = __cvta_generic_to_global(g);
    asm volatile("cp.async.cg.shared.global [%0], [%1], 16;" :: "r"(s), "l"(ga) : "memory");
}

#define LDM_X4(r0,r1,r2,r3,addr) \
    asm volatile("ldmatrix.sync.aligned.m8n8.x4.shared.b16 {%0,%1,%2,%3}, [%4];" \
        : "=r"(r0),"=r"(r1),"=r"(r2),"=r"(r3) : "r"(addr))

#define MMA16816(d, a, b0, b1) \
    asm volatile("mma.sync.aligned.m16n8k16.row.col.f32.f16.f16.f32 " \
        "{%0,%1,%2,%3},{%4,%5,%6,%7},{%8,%9},{%0,%1,%2,%3};" \
        : "+f"((d)[0]),"+f"((d)[1]),"+f"((d)[2]),"+f"((d)[3]) \
        : "r"((a)[0]),"r"((a)[1]),"r"((a)[2]),"r"((a)[3]),"r"(b0),"r"(b1))

// ------------- precompute kernels -------------
__global__ void split_feat(const float* __restrict__ A) {
    size_t i = (size_t)blockIdx.x * blockDim.x + threadIdx.x;   // 8 elems each
    if (i >= (size_t)NROWS * DIMD / 8) return;
    const float4* a4 = reinterpret_cast<const float4*>(A) + i * 2;
    float4 v0 = a4[0], v1 = a4[1];
    float x[8] = {v0.x, v0.y, v0.z, v0.w, v1.x, v1.y, v1.z, v1.w};
    __half h[8];
    #pragma unroll
    for (int j = 0; j < 8; j++) h[j] = __float2half_rn(x[j]);
    reinterpret_cast<uint4*>(g_Ahi)[i] = *reinterpret_cast<uint4*>(h);
}

// 32x32 smem tile transpose: B [d][k] -> g_Bt/g_Bhi [k][d], coalesced both sides
__global__ __launch_bounds__(256) void split_cent(const float* __restrict__ B) {
    __shared__ float tile[32][33];
    const int k0 = (blockIdx.x & 31) * 32;
    const int d0 = (blockIdx.x >> 5) * 32;
    const int tx = threadIdx.x & 31;
    const int ty = threadIdx.x >> 5;          // 0..7
    #pragma unroll
    for (int j = 0; j < 32; j += 8)
        tile[ty + j][tx] = B[(size_t)(d0 + ty + j) * KCOLS + k0 + tx];
    __syncthreads();
    #pragma unroll
    for (int j = 0; j < 32; j += 8) {
        float v = tile[tx][ty + j];
        size_t o = (size_t)(k0 + ty + j) * DIMD + d0 + tx;
        g_Bt[o]  = v;
        g_Bhi[o] = __float2half_rn(v);
    }
}

// one warp per centroid, reads contiguous g_Bt rows
__global__ __launch_bounds__(256) void csq_kernel() {
    const int k = blockIdx.x * 8 + (threadIdx.x >> 5);
    const int lane = threadIdx.x & 31;
    const float4* b4 = reinterpret_cast<const float4*>(g_Bt + (size_t)k * DIMD);
    float s = 0.f;
    #pragma unroll
    for (int i = 0; i < 4; i++) {
        float4 v = b4[lane + 32 * i];
        s = fmaf(v.x, v.x, s); s = fmaf(v.y, v.y, s);
        s = fmaf(v.z, v.z, s); s = fmaf(v.w, v.w, s);
    }
    #pragma unroll
    for (int o = 16; o > 0; o >>= 1) s += __shfl_xor_sync(0xFFFFFFFFu, s, o);
    if (lane == 0) g_csq[k] = s;
}

// ------------- phase 1: warp-tile 2x8 fp16 screen + top-2/thread -> top-4/row -------------
__global__ __launch_bounds__(THREADS, 2) void assign_mma() {
    extern __shared__ char smem[];
    const uint32_t sb = smem_u32(smem);
    const int tid = threadIdx.x;
    const int lane = tid & 31;
    const int w = tid >> 5;
    const int mw = w & 3;           // 0..3 (M), 32 rows each
    const int nwp = w >> 2;         // 0..1 (N), 64 cols each
    const int row0 = blockIdx.x * MT;
    float* csq_s = reinterpret_cast<float*>(smem + SM_CSQ);

    // ldmatrix address precomputes (within a 64-d sub-array, 128 rows x 128B)
    uint32_t aBase[2], aM[2], bBase[4], bM[4];
    #pragma unroll
    for (int mi = 0; mi < 2; mi++) {
        int r = mw * 32 + mi * 16 + (lane & 15);
        aBase[mi] = (uint32_t)r * 128;
        aM[mi] = (uint32_t)(r & 7) * 16;
    }
    #pragma unroll
    for (int nb = 0; nb < 4; nb++) {
        int r = nwp * 64 + nb * 16 + ((lane & 7) + ((lane >> 4) << 3));
        bBase[nb] = (uint32_t)r * 128;
        bM[nb] = (uint32_t)(r & 7) * 16;
    }
    const uint32_t aU = (uint32_t)(lane >> 4) * 16;        // 0 or 16
    const uint32_t bU = (uint32_t)((lane >> 3) & 1) * 16;  // 0 or 16

    // per-thread cp.async source pointers (hoisted 64-bit address math)
    const __half* aSrc[4];
    const __half* bSrc[4];
    uint32_t soA[4], soB[4];
    #pragma unroll
    for (int q = 0; q < 4; q++) {
        int idx = tid + THREADS * q;        // 0..1023 16B units
        int r = idx >> 3, u = idx & 7;
        uint32_t so = sw128((uint32_t)r * 128 + (uint32_t)u * 16);
        soA[q] = so;
        soB[q] = so;
        aSrc[q] = g_Ahi + (size_t)(row0 + r) * DIMD + u * 8;
        bSrc[q] = g_Bhi + (size_t)r * DIMD + u * 8;
    }

    float acc1[2][8][4];
    float v1[4], v2[4];
    int   i1[4], i2[4];
    #pragma unroll
    for (int i = 0; i < 4; i++) { v1[i] = 3.4e38f; v2[i] = 3.4e38f; i1[i] = 0; i2[i] = 0; }

    auto load_stage = [&](int stg, int it) {
        const int nt = it >> 3, dc = it & 7;
        const int aOff = dc * KB;
        const int bOff = nt * NT * DIMD + dc * KB;
        uint32_t sbase = sb + SM_TILES + (uint32_t)stg * STAGE_B;
        #pragma unroll
        for (int q = 0; q < 4; q++) cp16(sbase + soA[q], aSrc[q] + aOff);
        #pragma unroll
        for (int q = 0; q < 4; q++) cp16(sbase + A_SUB + soB[q], bSrc[q] + bOff);
        asm volatile("cp.async.commit_group;" ::: "memory");
    };

    load_stage(0, 0);
    load_stage(1, 1);

    for (int it = 0; it < NIT; it++) {
        const int nt = it >> 3, dc = it & 7, stg = it % NSTAGE;
        asm volatile("cp.async.wait_group %0;" :: "n"(NSTAGE - 2) : "memory");
        __syncthreads();
        if (it + NSTAGE - 1 < NIT)
            load_stage((it + NSTAGE - 1) % NSTAGE, it + NSTAGE - 1);

        if (dc == 0) {
            if (tid < NT) csq_s[tid] = g_csq[nt * NT + tid];
            #pragma unroll
            for (int mi = 0; mi < 2; mi++)
                #pragma unroll
                for (int ni = 0; ni < 8; ni++)
                    #pragma unroll
                    for (int e = 0; e < 4; e++) acc1[mi][ni][e] = 0.f;
        }

        // ---- compute chunk: 6 LDM feed 16 MMAs per k16 ----
        const uint32_t subA = sb + SM_TILES + (uint32_t)stg * STAGE_B;
        const uint32_t subB = subA + A_SUB;
        #pragma unroll
        for (int k16 = 0; k16 < 4; k16++) {
            const uint32_t ka = (uint32_t)k16 * 32 + aU;
            const uint32_t kb = (uint32_t)k16 * 32 + bU;
            uint32_t ahi[2][4], bhi[4][4];
            #pragma unroll
            for (int mi = 0; mi < 2; mi++)
                LDM_X4(ahi[mi][0], ahi[mi][1], ahi[mi][2], ahi[mi][3],
                       subA + aBase[mi] + (ka ^ aM[mi]));
            #pragma unroll
            for (int nb = 0; nb < 4; nb++)
                LDM_X4(bhi[nb][0], bhi[nb][1], bhi[nb][2], bhi[nb][3],
                       subB + bBase[nb] + (kb ^ bM[nb]));
            #pragma unroll
            for (int mi = 0; mi < 2; mi++)
                #pragma unroll
                for (int ni = 0; ni < 8; ni++)
                    MMA16816(acc1[mi][ni], ahi[mi],
                             bhi[ni >> 1][(ni & 1) * 2], bhi[ni >> 1][(ni & 1) * 2 + 1]);
        }

        if (dc == DCH - 1) {
            // fold this column tile into per-thread top-2 (registers only)
            #pragma unroll
            for (int mi = 0; mi < 2; mi++)
                #pragma unroll
                for (int half = 0; half < 2; half++) {
                    const int rs = mi * 2 + half;
                    #pragma unroll
                    for (int ni = 0; ni < 8; ni++)
                        #pragma unroll
                        for (int e = 0; e < 2; e++) {
                            const int cl = nwp * 64 + ni * 8 + (lane & 3) * 2 + e;
                            const int col = nt * NT + cl;
                            float dist = csq_s[cl] - 2.0f * acc1[mi][ni][half * 2 + e];
                            if (dist < v1[rs]) {
                                v2[rs] = v1[rs]; i2[rs] = i1[rs];
                                v1[rs] = dist;   i1[rs] = col;
                            } else if (dist < v2[rs]) {
                                v2[rs] = dist; i2[rs] = col;
                            }
                        }
                }
        }
    }
    __syncthreads();

    // ---- dump per-thread top-2: 8 threads per row (4 lane-groups x 2 N-warps) ----
    float4* cand = reinterpret_cast<float4*>(smem + SM_TILES);   // [row][slot], 128x8
    {
        const int slot = nwp * 4 + (lane & 3);
        #pragma unroll
        for (int rs = 0; rs < 4; rs++) {
            int row = mw * 32 + (rs >> 1) * 16 + (rs & 1) * 8 + (lane >> 2);
            cand[row * 8 + slot] = make_float4(v1[rs], __int_as_float(i1[rs]),
                                               v2[rs], __int_as_float(i2[rs]));
        }
    }
    __syncthreads();

    // ---- one thread per row: top-4 of 16 candidates (lexicographic) ----
    if (tid < MT) {
        float t1 = 3.4e38f, t2 = 3.4e38f, t3 = 3.4e38f, t4 = 3.4e38f;
        int   j1 = 0, j2 = 0, j3 = 0, j4 = 0;
        #pragma unroll 4
        for (int t = 0; t < 8; t++) {
            float4 c = cand[tid * 8 + t];
            #pragma unroll
            for (int h = 0; h < 2; h++) {
                float v = h ? c.z : c.x;
                int   i = __float_as_int(h ? c.w : c.y);
                if (v < t1 || (v == t1 && i < j1)) {
                    t4 = t3; j4 = j3; t3 = t2; j3 = j2; t2 = t1; j2 = j1; t1 = v; j1 = i;
                } else if (v < t2 || (v == t2 && i < j2)) {
                    t4 = t3; j4 = j3; t3 = t2; j3 = j2; t2 = v; j2 = i;
                } else if (v < t3 || (v == t3 && i < j3)) {
                    t4 = t3; j4 = j3; t3 = v; j3 = i;
                } else if (v < t4 || (v == t4 && i < j4)) {
                    t4 = v; j4 = i;
                }
            }
        }
        g_cand[row0 + tid] = make_int4(j1, j2, j3, j4);
    }
}

// ------------- phase 2: exact fp32 rescue — one warp per row, coalesced -------------
__global__ __launch_bounds__(256) void rescue_kernel(const float* __restrict__ A,
                                                     float* __restrict__ out) {
    const int row = blockIdx.x * 8 + (threadIdx.x >> 5);
    const int lane = threadIdx.x & 31;
    const int4 cd = g_cand[row];   // same addr across warp -> broadcast

    const float4* a4 = reinterpret_cast<const float4*>(A + (size_t)row * DIMD);
    float4 av[4];
    #pragma unroll
    for (int i = 0; i < 4; i++) av[i] = a4[lane + 32 * i];

    int cands[4] = {cd.x, cd.y, cd.z, cd.w};
    float bv = 3.4e38f;
    int   bi = 0x7FFFFFFF;
    #pragma unroll
    for (int c = 0; c < 4; c++) {
        const float4* b4 = reinterpret_cast<const float4*>(g_Bt + (size_t)cands[c] * DIMD);
        float s = 0.f;
        #pragma unroll
        for (int i = 0; i < 4; i++) {
            float4 bvq = b4[lane + 32 * i];   // coalesced; g_Bt is L2-hot (2MB)
            s = fmaf(av[i].x, bvq.x, s);
            s = fmaf(av[i].y, bvq.y, s);
            s = fmaf(av[i].z, bvq.z, s);
            s = fmaf(av[i].w, bvq.w, s);
        }
        #pragma unroll
        for (int o = 16; o > 0; o >>= 1) s += __shfl_xor_sync(0xFFFFFFFFu, s, o);
        float dist = g_csq[cands[c]] - 2.0f * s;
        if (dist < bv || (dist == bv && cands[c] < bi)) { bv = dist; bi = cands[c]; }
    }
    if (lane == 0) out[row] = (float)bi;
}

// ------------- launch -------------
extern "C" void kernel_launch(void* const* d_in, const int* in_sizes, int n_in,
                              void* d_out, int out_size) {
    const float* features  = (const float*)d_in[0];   // [131072, 512]
    const float* centroids = (const float*)d_in[1];   // [512, 1024]
    float* out = (float*)d_out;

    cudaFuncSetAttribute(assign_mma, cudaFuncAttributeMaxDynamicSharedMemorySize, SMEM_TOTAL);

    split_feat<<<(int)(((size_t)NROWS * DIMD / 8 + 255) / 256), 256>>>(features);
    split_cent<<<(KCOLS / 32) * (DIMD / 32), 256>>>(centroids);
    csq_kernel<<<KCOLS / 8, 256>>>();
    assign_mma<<<NROWS / MT, THREADS, SMEM_TOTAL>>>();
    rescue_kernel<<<NROWS / 8, 256>>>(features, out);
}